// round 1
// baseline (speedup 1.0000x reference)
#include <cuda_runtime.h>

#define NB   2
#define NC   512
#define NN   4096
#define NUU  1024
#define NHEAD 8
#define HD   64
#define SCALE_ 0.125f

// ---------------- scratch (device globals; no allocation allowed) ----------
__device__ float g_q     [NB*NHEAD*NN*HD];        // [b,h,n,d]
__device__ float g_fk    [NB*NHEAD*NN*HD];
__device__ float g_fv    [NB*NHEAD*NN*HD];
__device__ float g_k     [NB*NHEAD*NUU*HD];       // [b,h,m,d]
__device__ float g_v     [NB*NHEAD*NUU*HD];
__device__ float g_sim   [(size_t)NB*NHEAD*NN*NUU]; // 268MB, softmax in place
__device__ float g_coarse[NB*NHEAD*NN*HD];
__device__ float g_xsum  [NB*NC*NN];              // x_out (+ v_pe) in [b,c,n]
__device__ float g_heat  [NB*NUU];
__device__ float g_qmean [NB*NHEAD*HD];
__device__ int   g_idxf  [NB*NHEAD*64];
__device__ float g_pet   [NB*NC*NUU];             // depthwise conv result

// ---------------- generic conv1x1 GEMM: out = W[O,K] @ X[b][K,N] + bias ----
// MODE 0: write g_q head layout (O=512)
// MODE 1: write g_fk/g_fv head layout (O=1024, N=4096)
// MODE 3: write g_k/g_v head layout  (O=1024, N=1024)
// MODE 2: read g_xsum, write out [b,O,N]
template<int MODE>
__global__ void conv_gemm(const float* __restrict__ X, const float* __restrict__ W,
                          const float* __restrict__ bias, float* __restrict__ out,
                          int O, int K, int N)
{
    __shared__ float Ws[16][64];
    __shared__ float Xs[16][64];
    int b = blockIdx.z;
    int otile = blockIdx.y * 64, ntile = blockIdx.x * 64;
    int tid = threadIdx.x;
    int tx = tid & 15, ty = tid >> 4;
    const float* Xb = (MODE == 2 ? g_xsum : X) + (size_t)b * K * N;

    float acc[4][4] = {};
    for (int kk = 0; kk < K; kk += 16) {
#pragma unroll
        for (int it = 0; it < 4; it++) {
            int e = tid + it * 256;
            int k = e & 15, o = e >> 4;
            Ws[k][o] = W[(size_t)(otile + o) * K + kk + k];
        }
#pragma unroll
        for (int it = 0; it < 4; it++) {
            int e = tid + it * 256;
            int n = e & 63, k = e >> 6;
            Xs[k][n] = Xb[(size_t)(kk + k) * N + ntile + n];
        }
        __syncthreads();
#pragma unroll
        for (int k = 0; k < 16; k++) {
            float4 a4 = *(const float4*)&Ws[k][ty * 4];
            float4 x4 = *(const float4*)&Xs[k][tx * 4];
            float av[4] = {a4.x, a4.y, a4.z, a4.w};
            float xv[4] = {x4.x, x4.y, x4.z, x4.w};
#pragma unroll
            for (int i = 0; i < 4; i++)
#pragma unroll
                for (int j = 0; j < 4; j++)
                    acc[i][j] += av[i] * xv[j];
        }
        __syncthreads();
    }
#pragma unroll
    for (int i = 0; i < 4; i++) {
        int o = otile + ty * 4 + i;
        float bv = bias[o];
#pragma unroll
        for (int j = 0; j < 4; j++) {
            int n = ntile + tx * 4 + j;
            float v = acc[i][j] + bv;
            if (MODE == 0) {
                int h = o >> 6, d = o & 63;
                g_q[(((size_t)(b * NHEAD + h)) * NN + n) * HD + d] = v;
            } else if (MODE == 1) {
                int h = o >> 7, r = o & 127;
                float* p = (r < 64) ? g_fk : g_fv;
                p[(((size_t)(b * NHEAD + h)) * NN + n) * HD + (r & 63)] = v;
            } else if (MODE == 3) {
                int h = o >> 7, r = o & 127;
                float* p = (r < 64) ? g_k : g_v;
                p[(((size_t)(b * NHEAD + h)) * NUU + n) * HD + (r & 63)] = v;
            } else {
                out[((size_t)b * O + o) * (size_t)N + n] = v;
            }
        }
    }
}

// ---------------- sim = q @ k^T * scale (per bh), K-dim = 64 ---------------
__global__ void sim_gemm()
{
    __shared__ float As[16][64]; // [d][n]
    __shared__ float Bs[16][64]; // [d][m]
    int bh = blockIdx.z;
    int ntile = blockIdx.y * 64, mtile = blockIdx.x * 64;
    const float* Q  = g_q + (size_t)bh * NN * HD;
    const float* Kp = g_k + (size_t)bh * NUU * HD;
    int tid = threadIdx.x, tx = tid & 15, ty = tid >> 4;
    float acc[4][4] = {};
    for (int kk = 0; kk < HD; kk += 16) {
#pragma unroll
        for (int it = 0; it < 4; it++) {
            int e = tid + it * 256;
            int d = e & 15, n = e >> 4;
            As[d][n] = Q[(size_t)(ntile + n) * HD + kk + d];
        }
#pragma unroll
        for (int it = 0; it < 4; it++) {
            int e = tid + it * 256;
            int d = e & 15, m = e >> 4;
            Bs[d][m] = Kp[(size_t)(mtile + m) * HD + kk + d];
        }
        __syncthreads();
#pragma unroll
        for (int k = 0; k < 16; k++) {
            float4 a4 = *(const float4*)&As[k][ty * 4];
            float4 b4 = *(const float4*)&Bs[k][tx * 4];
            float av[4] = {a4.x, a4.y, a4.z, a4.w};
            float bv[4] = {b4.x, b4.y, b4.z, b4.w};
#pragma unroll
            for (int i = 0; i < 4; i++)
#pragma unroll
                for (int j = 0; j < 4; j++)
                    acc[i][j] += av[i] * bv[j];
        }
        __syncthreads();
    }
    float* S = g_sim + (size_t)bh * NN * NUU;
#pragma unroll
    for (int i = 0; i < 4; i++)
#pragma unroll
        for (int j = 0; j < 4; j++)
            S[(size_t)(ntile + ty * 4 + i) * NUU + mtile + tx * 4 + j] = acc[i][j] * SCALE_;
}

// ---------------- rowwise softmax over 1024, in place -----------------------
__global__ void softmax_kernel()
{
    size_t row = blockIdx.x;
    float* p = g_sim + row * NUU;
    int t = threadIdx.x;
    __shared__ float red[256];
    float v[4];
    float mx = -1e30f;
#pragma unroll
    for (int i = 0; i < 4; i++) { v[i] = p[t + i * 256]; mx = fmaxf(mx, v[i]); }
    red[t] = mx; __syncthreads();
    for (int off = 128; off; off >>= 1) {
        if (t < off) red[t] = fmaxf(red[t], red[t + off]);
        __syncthreads();
    }
    mx = red[0]; __syncthreads();
    float s = 0.f;
#pragma unroll
    for (int i = 0; i < 4; i++) { v[i] = __expf(v[i] - mx); s += v[i]; }
    red[t] = s; __syncthreads();
    for (int off = 128; off; off >>= 1) {
        if (t < off) red[t] += red[t + off];
        __syncthreads();
    }
    float inv = 1.f / red[0];
#pragma unroll
    for (int i = 0; i < 4; i++) p[t + i * 256] = v[i] * inv;
}

// ---------------- coarse = attn @ v (per bh), K-dim = 1024 ------------------
__global__ void av_gemm()
{
    __shared__ float As[16][64]; // [m][n]
    __shared__ float Bs[16][64]; // [m][d]
    int bh = blockIdx.z;
    int ntile = blockIdx.y * 64;
    const float* A  = g_sim + (size_t)bh * NN * NUU;
    const float* Vp = g_v + (size_t)bh * NUU * HD;
    int tid = threadIdx.x, tx = tid & 15, ty = tid >> 4;
    float acc[4][4] = {};
    for (int kk = 0; kk < NUU; kk += 16) {
#pragma unroll
        for (int it = 0; it < 4; it++) {
            int e = tid + it * 256;
            int k = e & 15, n = e >> 4;
            As[k][n] = A[(size_t)(ntile + n) * NUU + kk + k];
        }
        {
            int e = tid; // 1024 floats / 256 threads = 4, but do strided
#pragma unroll
            for (int it = 0; it < 4; it++) {
                int ee = e + it * 256;
                int d = ee & 63, k = ee >> 6;
                Bs[k][d] = Vp[(size_t)(kk + k) * HD + d];
            }
        }
        __syncthreads();
#pragma unroll
        for (int k = 0; k < 16; k++) {
            float4 a4 = *(const float4*)&As[k][ty * 4];
            float4 b4 = *(const float4*)&Bs[k][tx * 4];
            float av[4] = {a4.x, a4.y, a4.z, a4.w};
            float bv[4] = {b4.x, b4.y, b4.z, b4.w};
#pragma unroll
            for (int i = 0; i < 4; i++)
#pragma unroll
                for (int j = 0; j < 4; j++)
                    acc[i][j] += av[i] * bv[j];
        }
        __syncthreads();
    }
    float* O = g_coarse + (size_t)bh * NN * HD;
#pragma unroll
    for (int i = 0; i < 4; i++)
#pragma unroll
        for (int j = 0; j < 4; j++)
            O[(size_t)(ntile + ty * 4 + i) * HD + tx * 4 + j] = acc[i][j];
}

// ---------------- heat: channel-mean + 2x2 pool -----------------------------
__global__ void heat_kernel(const float* __restrict__ x)
{
    int bm = blockIdx.x;
    int b = bm >> 10, m = bm & 1023;
    int hu = m >> 5, wu = m & 31;
    int p00 = (2 * hu) * 64 + 2 * wu;
    int t = threadIdx.x;
    __shared__ float red[256];
    float s = 0.f;
    for (int c = t; c < NC; c += 256) {
        const float* xp = x + ((size_t)b * NC + c) * NN;
        s += xp[p00] + xp[p00 + 1] + xp[p00 + 64] + xp[p00 + 65];
    }
    red[t] = s; __syncthreads();
    for (int off = 128; off; off >>= 1) {
        if (t < off) red[t] += red[t + off];
        __syncthreads();
    }
    if (t == 0) g_heat[bm] = red[0] * (1.f / 2048.f);
}

// ---------------- qmean: mean over n of q[b,h,:,d] ---------------------------
__global__ void qmean_kernel()
{
    int bh = blockIdx.x;
    int t = threadIdx.x;
    int d = t & 63, seg = t >> 6;
    float s = 0.f;
    const float* Q = g_q + (size_t)bh * NN * HD;
    for (int n = seg * 1024; n < seg * 1024 + 1024; n++) s += Q[(size_t)n * HD + d];
    __shared__ float red[256];
    red[t] = s; __syncthreads();
    if (seg == 0)
        g_qmean[bh * HD + d] = (red[d] + red[64 + d] + red[128 + d] + red[192 + d]) * (1.f / (float)NN);
}

// ---------------- global scores + top-16 + idx_full --------------------------
__global__ void topk_kernel(const float* __restrict__ gumbel)
{
    int bh = blockIdx.x;
    int b = bh >> 3;
    int t = threadIdx.x;
    __shared__ float s[NUU];
    __shared__ float qm[HD];
    __shared__ float rv[256];
    __shared__ int   ri[256];
    if (t < HD) qm[t] = g_qmean[bh * HD + t];
    __syncthreads();
    for (int m = t; m < NUU; m += 256) {
        const float* kp = g_k + ((size_t)bh * NUU + m) * HD;
        float dot = 0.f;
#pragma unroll
        for (int d = 0; d < HD; d++) dot += qm[d] * kp[d];
        s[m] = dot * SCALE_ * g_heat[b * NUU + m] + gumbel[(size_t)bh * NUU + m];
    }
    __syncthreads();
    for (int it = 0; it < 16; it++) {
        float bv = -1e30f; int bi = 0x7fffffff;
        for (int m = t; m < NUU; m += 256) {
            float v = s[m];
            if (v > bv || (v == bv && m < bi)) { bv = v; bi = m; }
        }
        rv[t] = bv; ri[t] = bi; __syncthreads();
        for (int off = 128; off; off >>= 1) {
            if (t < off) {
                float v2 = rv[t + off]; int i2 = ri[t + off];
                if (v2 > rv[t] || (v2 == rv[t] && i2 < ri[t])) { rv[t] = v2; ri[t] = i2; }
            }
            __syncthreads();
        }
        if (t == 0) {
            int m = ri[0];
            s[m] = -1e38f;
            int hi = (m >> 5) * 2, wi = (m & 31) * 2;
            int base = hi * 64 + wi;
            g_idxf[bh * 64 +       it] = base;
            g_idxf[bh * 64 + 16 +  it] = base + 1;
            g_idxf[bh * 64 + 32 +  it] = base + 64;
            g_idxf[bh * 64 + 48 +  it] = base + 65;
        }
        __syncthreads();
    }
}

// ---------------- fine attention + gate + blend -> g_xsum --------------------
struct FineSmem {
    float Ks[64][65];
    float Vs[64][64];
    float Gw[128][64];   // transposed gate_w
    float Os[64][65];    // [d][n_local] for coalesced store
    int   idx[64];
    float gb[64];
};

__global__ void fine_kernel(const float* __restrict__ gate_w, const float* __restrict__ gate_b)
{
    extern __shared__ char smem_raw[];
    FineSmem* S = reinterpret_cast<FineSmem*>(smem_raw);
    int bh = blockIdx.y;
    int b = bh >> 3, h = bh & 7;
    int ntile = blockIdx.x * 64;
    int t = threadIdx.x;

    if (t < 64) { S->idx[t] = g_idxf[bh * 64 + t]; S->gb[t] = gate_b[t]; }
    for (int e = t; e < 8192; e += 256) {
        int o = e >> 7, c = e & 127;
        S->Gw[c][o] = gate_w[e];
    }
    __syncthreads();
    for (int e = t; e < 4096; e += 256) {
        int m = e >> 6, d = e & 63;
        size_t src = ((size_t)bh * NN + S->idx[m]) * HD + d;
        S->Ks[m][d] = g_fk[src];
        S->Vs[m][d] = g_fv[src];
    }
    __syncthreads();

    int w = t >> 5, l = t & 31;
    for (int qi = 0; qi < 8; qi++) {
        int n = ntile + w * 8 + qi;
        const float* qp = g_q + ((size_t)bh * NN + n) * HD;
        float q0 = qp[l], q1 = qp[l + 32];
        float s0 = 0.f, s1 = 0.f;
#pragma unroll
        for (int d = 0; d < 64; d++) {
            float qd = __shfl_sync(0xffffffffu, d < 32 ? q0 : q1, d & 31);
            s0 += qd * S->Ks[l][d];
            s1 += qd * S->Ks[l + 32][d];
        }
        s0 *= SCALE_; s1 *= SCALE_;
        float mx = fmaxf(s0, s1);
#pragma unroll
        for (int off = 16; off; off >>= 1) mx = fmaxf(mx, __shfl_xor_sync(0xffffffffu, mx, off));
        float p0 = __expf(s0 - mx), p1 = __expf(s1 - mx);
        float sm = p0 + p1;
#pragma unroll
        for (int off = 16; off; off >>= 1) sm += __shfl_xor_sync(0xffffffffu, sm, off);
        float inv = 1.f / sm;
        p0 *= inv; p1 *= inv;

        float r0 = 0.f, r1 = 0.f;
#pragma unroll
        for (int m = 0; m < 64; m++) {
            float pm = __shfl_sync(0xffffffffu, m < 32 ? p0 : p1, m & 31);
            r0 += pm * S->Vs[m][l];
            r1 += pm * S->Vs[m][l + 32];
        }
        const float* cp = g_coarse + ((size_t)bh * NN + n) * HD;
        float c0 = cp[l], c1 = cp[l + 32];

        float g0 = S->gb[l], g1 = S->gb[l + 32];
#pragma unroll
        for (int c = 0; c < 64; c++) {
            float cv = __shfl_sync(0xffffffffu, c < 32 ? c0 : c1, c & 31);
            g0 += cv * S->Gw[c][l];
            g1 += cv * S->Gw[c][l + 32];
        }
#pragma unroll
        for (int c = 0; c < 64; c++) {
            float rvv = __shfl_sync(0xffffffffu, c < 32 ? r0 : r1, c & 31);
            g0 += rvv * S->Gw[64 + c][l];
            g1 += rvv * S->Gw[64 + c][l + 32];
        }
        g0 = 1.f / (1.f + __expf(-g0));
        g1 = 1.f / (1.f + __expf(-g1));
        int nl = w * 8 + qi;
        S->Os[l][nl]      = g0 * r0 + (1.f - g0) * c0;
        S->Os[l + 32][nl] = g1 * r1 + (1.f - g1) * c1;
    }
    __syncthreads();
    for (int e = t; e < 4096; e += 256) {
        int d = e >> 6, nl = e & 63;
        g_xsum[((size_t)b * NC + h * 64 + d) * NN + ntile + nl] = S->Os[d][nl];
    }
}

// ---------------- depthwise 7x7 conv on v_rs [B,C,32,32] ---------------------
__global__ void pe_conv(const float* __restrict__ pe_w, const float* __restrict__ pe_b)
{
    int bc = blockIdx.x;
    int b = bc >> 9, c = bc & 511;
    int h = c >> 6, d = c & 63;
    __shared__ float img[1024];
    __shared__ float wt[49];
    int t = threadIdx.x;
    for (int p = t; p < 1024; p += 256)
        img[p] = g_v[((size_t)(b * NHEAD + h) * NUU + p) * HD + d];
    if (t < 49) wt[t] = pe_w[c * 49 + t];
    __syncthreads();
    float bias = pe_b[c];
    for (int p = t; p < 1024; p += 256) {
        int y = p >> 5, xx0 = p & 31;
        float s = bias;
#pragma unroll
        for (int ky = 0; ky < 7; ky++) {
            int yy = y + ky - 3;
            if (yy < 0 || yy > 31) continue;
#pragma unroll
            for (int kx = 0; kx < 7; kx++) {
                int xx = xx0 + kx - 3;
                if (xx < 0 || xx > 31) continue;
                s += wt[ky * 7 + kx] * img[yy * 32 + xx];
            }
        }
        g_pet[(size_t)bc * 1024 + p] = s;
    }
}

// ---------------- bilinear upsample 32->64 (half-pixel) + accumulate --------
__global__ void bilinear_add()
{
    int bc = blockIdx.x;
    __shared__ float img[1024];
    int t = threadIdx.x;
    for (int p = t; p < 1024; p += 256) img[p] = g_pet[(size_t)bc * 1024 + p];
    __syncthreads();
    for (int p = t; p < 4096; p += 256) {
        int i = p >> 6, j = p & 63;
        int ti = i >> 1, tj = j >> 1;
        int y0, y1, x0, x1; float wy0, wy1, wx0, wx1;
        if (i & 1) { y0 = ti; y1 = min(ti + 1, 31); wy0 = 0.75f; wy1 = 0.25f; }
        else       { y0 = max(ti - 1, 0); y1 = ti;  wy0 = 0.25f; wy1 = 0.75f; }
        if (j & 1) { x0 = tj; x1 = min(tj + 1, 31); wx0 = 0.75f; wx1 = 0.25f; }
        else       { x0 = max(tj - 1, 0); x1 = tj;  wx0 = 0.25f; wx1 = 0.75f; }
        float v = wy0 * (wx0 * img[y0 * 32 + x0] + wx1 * img[y0 * 32 + x1])
                + wy1 * (wx0 * img[y1 * 32 + x0] + wx1 * img[y1 * 32 + x1]);
        g_xsum[(size_t)bc * 4096 + p] += v;
    }
}

// ---------------- launch ------------------------------------------------------
extern "C" void kernel_launch(void* const* d_in, const int* in_sizes, int n_in,
                              void* d_out, int out_size)
{
    const float* x      = (const float*)d_in[0];
    const float* upper  = (const float*)d_in[1];
    const float* gumbel = (const float*)d_in[2];
    const float* q_w    = (const float*)d_in[3];
    const float* q_b    = (const float*)d_in[4];
    const float* kv_w   = (const float*)d_in[5];
    const float* kv_b   = (const float*)d_in[6];
    const float* proj_w = (const float*)d_in[7];
    const float* proj_b = (const float*)d_in[8];
    const float* pe_w   = (const float*)d_in[9];
    const float* pe_b   = (const float*)d_in[10];
    const float* gate_w = (const float*)d_in[11];
    const float* gate_b = (const float*)d_in[12];
    float* out = (float*)d_out;

    cudaFuncSetAttribute(fine_kernel, cudaFuncAttributeMaxDynamicSharedMemorySize,
                         (int)sizeof(FineSmem));

    dim3 blk(256);
    // q = conv1x1(x, q_w) -> g_q
    conv_gemm<0><<<dim3(NN / 64, NC / 64, NB), blk>>>(x, q_w, q_b, nullptr, 512, 512, NN);
    // f_kv = conv1x1(x, kv_w) -> g_fk/g_fv
    conv_gemm<1><<<dim3(NN / 64, 1024 / 64, NB), blk>>>(x, kv_w, kv_b, nullptr, 1024, 512, NN);
    // kv = conv1x1(upper, kv_w) -> g_k/g_v
    conv_gemm<3><<<dim3(NUU / 64, 1024 / 64, NB), blk>>>(upper, kv_w, kv_b, nullptr, 1024, 512, NUU);

    heat_kernel<<<NB * NUU, blk>>>(x);
    qmean_kernel<<<NB * NHEAD, blk>>>();
    topk_kernel<<<NB * NHEAD, blk>>>(gumbel);

    sim_gemm<<<dim3(NUU / 64, NN / 64, NB * NHEAD), blk>>>();
    softmax_kernel<<<NB * NHEAD * NN, blk>>>();
    av_gemm<<<dim3(1, NN / 64, NB * NHEAD), blk>>>();

    fine_kernel<<<dim3(NN / 64, NB * NHEAD), blk, sizeof(FineSmem)>>>(gate_w, gate_b);

    pe_conv<<<NB * NC, blk>>>(pe_w, pe_b);
    bilinear_add<<<NB * NC, blk>>>();

    // final proj: reads g_xsum, writes d_out [B,512,64,64]
    conv_gemm<2><<<dim3(NN / 64, NC / 64, NB), blk>>>(nullptr, proj_w, proj_b, out, 512, 512, NN);
}